// round 16
// baseline (speedup 1.0000x reference)
#include <cuda_runtime.h>
#include <cuda_bf16.h>
#include <cstdint>

// ConjunctionLayer via mma.sync bf16 tensor cores:
// s[b,j] = sum_k ln(1 + a_k w_k) = sum_{n=1..6} c_n dot(a^n, w^n)  (Mercator)
// term 1 split hi/lo both sides -> 8 GEMM slots; out = -1/(s-1).
// KSPLIT=8: each CTA computes ONE slot over K=512 for a 64-row m-tile.
// 128-thread CTAs, 4 CTAs/SM -> 4 independent barrier/pipeline domains per SM.
// A: coalesced x load -> slot power -> bf16 -> smem (double buffer) -> ldmatrix.
// B: precomputed slot images, 3-stage cp.async pipeline (wait_group 1).
// Ticket-counter finalize over 8 partials, self-resetting (graph-safe).

#define Bdim 4096
#define Ddim 512
#define Ndim 128

#define MT     64
#define NMT    (Bdim / MT)      // 64 m-tiles
#define KSPLIT 8                // = number of series slots
#define NKC    16               // 32-k chunks per slot
#define AROW   80               // smem row stride bytes
#define IMGB   (128 * AROW)     // 10240 B per B chunk image
#define IMGA   (MT * AROW)      // 5120 B per A buffer
#define NSTAGE 3

__device__ uint4 g_bmat[128 * IMGB / 16];          // 1.31MB B slot images
__device__ float g_partial[KSPLIT][Bdim * Ndim];   // 16MB partial sums
__device__ int   g_cnt[NMT];                       // tickets (self-reset)

__device__ __forceinline__ uint32_t pack_bf16x2(float lo, float hi) {
    uint32_t d;
    asm("cvt.rn.bf16x2.f32 %0, %1, %2;" : "=r"(d) : "f"(hi), "f"(lo));
    return d;
}
__device__ __forceinline__ void cp16(uint32_t dst, const void* src) {
    asm volatile("cp.async.cg.shared.global [%0], [%1], 16;" :: "r"(dst), "l"(src));
}
__device__ __forceinline__ void ldsm4(uint32_t* r, uint32_t addr) {
    asm volatile("ldmatrix.sync.aligned.m8n8.x4.shared.b16 {%0,%1,%2,%3}, [%4];"
                 : "=r"(r[0]), "=r"(r[1]), "=r"(r[2]), "=r"(r[3]) : "r"(addr));
}
__device__ __forceinline__ void mma16816(float* c, const uint32_t* A,
                                         uint32_t b0, uint32_t b1) {
    asm volatile(
        "mma.sync.aligned.m16n8k16.row.col.f32.bf16.bf16.f32 "
        "{%0,%1,%2,%3}, {%4,%5,%6,%7}, {%8,%9}, {%0,%1,%2,%3};"
        : "+f"(c[0]), "+f"(c[1]), "+f"(c[2]), "+f"(c[3])
        : "r"(A[0]), "r"(A[1]), "r"(A[2]), "r"(A[3]), "r"(b0), "r"(b1));
}

// ---- B slot images (validated): img = t*NKC + kc ----
// t0: w  t1: w_lo  t2: w  t3: -w^2/2  t4: w^3/3  t5: -w^4/4  t6: w^5/5  t7: -w^6/6
__global__ void prep_w(const float* __restrict__ W) {
    int img = blockIdx.x;
    int t = img >> 4, kc = img & 15;
    int r = threadIdx.x >> 1, half = threadIdx.x & 1;
    const float* wp = &W[r * Ddim + kc * 32 + half * 16];
    uint32_t pk[8];
#pragma unroll
    for (int i = 0; i < 8; i++) {
        float w0 = wp[2 * i], w1 = wp[2 * i + 1];
        float v0, v1;
        switch (t) {
            case 0: case 2: v0 = w0; v1 = w1; break;
            case 1:
                v0 = w0 - __bfloat162float(__float2bfloat16(w0));
                v1 = w1 - __bfloat162float(__float2bfloat16(w1));
                break;
            case 3: v0 = -0.5f * w0 * w0; v1 = -0.5f * w1 * w1; break;
            case 4: v0 = w0 * w0 * w0 * (1.0f / 3.0f);
                    v1 = w1 * w1 * w1 * (1.0f / 3.0f); break;
            case 5: { float a2 = w0 * w0, b2 = w1 * w1;
                      v0 = -0.25f * a2 * a2; v1 = -0.25f * b2 * b2; } break;
            case 6: { float a2 = w0 * w0, b2 = w1 * w1;
                      v0 = a2 * a2 * w0 * 0.2f; v1 = b2 * b2 * w1 * 0.2f; } break;
            default: { float a2 = w0 * w0, b2 = w1 * w1;
                       v0 = -a2 * a2 * a2 * (1.0f / 6.0f);
                       v1 = -b2 * b2 * b2 * (1.0f / 6.0f); } break;
        }
        pk[i] = pack_bf16x2(v0, v1);
    }
    char* dst = (char*)g_bmat + img * IMGB + r * AROW + half * 32;
    ((uint4*)dst)[0] = make_uint4(pk[0], pk[1], pk[2], pk[3]);
    ((uint4*)(dst + 16))[0] = make_uint4(pk[4], pk[5], pk[6], pk[7]);
}

// ---- main fused GEMM ----
__global__ __launch_bounds__(128, 4)
void conj_mma(const float* __restrict__ x, float* __restrict__ out) {
    __shared__ __align__(128) char smem[NSTAGE * IMGB + 2 * IMGA];  // B0 B1 B2 A0 A1
    __shared__ int s_last;

    const int tid = threadIdx.x, wid = tid >> 5, lane = tid & 31;
    const int mtile = blockIdx.x >> 3, ks = blockIdx.x & 7;    // ks = slot
    const int b0 = mtile * MT;
    const int wm = wid >> 1, wn = wid & 1;    // warp tile 32(m) x 64(n)

    const uint32_t sb = (uint32_t)__cvta_generic_to_shared(smem);
    const uint32_t sA = sb + NSTAGE * IMGB;
    const uint32_t bLd = sb + (wn * 64 + (lane & 7) + ((lane >> 1) & 8)) * AROW
                            + ((lane & 8) << 1);
    const uint32_t aLd = sA + (wm * 32 + (lane & 15)) * AROW + (lane & 16);
    const uint32_t aSts = sA + (tid >> 1) * AROW + (tid & 1) * 32;

    float acc[2][8][4];
#pragma unroll
    for (int mt = 0; mt < 2; mt++)
#pragma unroll
        for (int nt = 0; nt < 8; nt++)
#pragma unroll
            for (int c = 0; c < 4; c++) acc[mt][nt][c] = 0.0f;

    // A staging: thread = (row tid>>1, k-half tid&1) -> 16 x's per chunk
    const float* xrow = &x[(b0 + (tid >> 1)) * Ddim + (tid & 1) * 16];
    float4 xc[4], xn[4];

#define LDX(KC, D)                                                            \
    do {                                                                      \
        _Pragma("unroll")                                                     \
        for (int q = 0; q < 4; q++)                                           \
            (D)[q] = *(const float4*)&xrow[(KC) * 32 + q * 4];                \
    } while (0)

    // build this CTA's slot power from 16 x's, pack, store to A buffer P
#define BUILD_A(SRC, P)                                                       \
    do {                                                                      \
        float a_[16], st[16];                                                 \
        _Pragma("unroll")                                                     \
        for (int q = 0; q < 4; q++) {                                         \
            a_[4*q+0] = (SRC)[q].x - 1.0f; a_[4*q+1] = (SRC)[q].y - 1.0f;     \
            a_[4*q+2] = (SRC)[q].z - 1.0f; a_[4*q+3] = (SRC)[q].w - 1.0f;     \
        }                                                                     \
        if (ks <= 1) {                                                        \
            _Pragma("unroll") for (int i = 0; i < 16; i++) st[i] = a_[i];     \
        } else if (ks == 2) {                                                 \
            _Pragma("unroll") for (int i = 0; i < 16; i++)                    \
                st[i] = a_[i] - __bfloat162float(__float2bfloat16(a_[i]));    \
        } else if (ks == 3) {                                                 \
            _Pragma("unroll") for (int i = 0; i < 16; i++)                    \
                st[i] = a_[i] * a_[i];                                        \
        } else if (ks == 4) {                                                 \
            _Pragma("unroll") for (int i = 0; i < 16; i++)                    \
                st[i] = a_[i] * a_[i] * a_[i];                                \
        } else if (ks == 5) {                                                 \
            _Pragma("unroll") for (int i = 0; i < 16; i++)                    \
                { float t2 = a_[i] * a_[i]; st[i] = t2 * t2; }                \
        } else if (ks == 6) {                                                 \
            _Pragma("unroll") for (int i = 0; i < 16; i++)                    \
                { float t2 = a_[i] * a_[i]; st[i] = t2 * t2 * a_[i]; }        \
        } else {                                                              \
            _Pragma("unroll") for (int i = 0; i < 16; i++)                    \
                { float t3 = a_[i] * a_[i] * a_[i]; st[i] = t3 * t3; }        \
        }                                                                     \
        uint32_t pk[8];                                                       \
        _Pragma("unroll") for (int i = 0; i < 8; i++)                         \
            pk[i] = pack_bf16x2(st[2*i], st[2*i+1]);                          \
        uint32_t ad = aSts + (P) * IMGA;                                      \
        asm volatile("st.shared.v4.b32 [%0], {%1,%2,%3,%4};"                  \
                     :: "r"(ad), "r"(pk[0]), "r"(pk[1]), "r"(pk[2]), "r"(pk[3])); \
        asm volatile("st.shared.v4.b32 [%0], {%1,%2,%3,%4};"                  \
                     :: "r"(ad + 16), "r"(pk[4]), "r"(pk[5]), "r"(pk[6]), "r"(pk[7])); \
    } while (0)

#define STAGE_B(KC, ST)                                                       \
    do {                                                                      \
        const char* src = (const char*)g_bmat + (ks * NKC + (KC)) * IMGB;     \
        _Pragma("unroll")                                                     \
        for (int q = 0; q < 5; q++) {                                         \
            int idx = tid + q * 128;                                          \
            if (idx < IMGB / 16)                                              \
                cp16(sb + (ST) * IMGB + idx * 16, src + idx * 16);            \
        }                                                                     \
        asm volatile("cp.async.commit_group;");                               \
    } while (0)

    // prologue: A0 built, B0+B1 in flight, x1 prefetched
    LDX(0, xc);
    BUILD_A(xc, 0);
    STAGE_B(0, 0);
    STAGE_B(1, 1);
    LDX(1, xn);

    for (int ch = 0; ch < NKC; ch++) {
        const int st = ch % NSTAGE;
        const int p  = ch & 1;
        asm volatile("cp.async.wait_group 1;");
        __syncthreads();   // B[ch] staged; A[p] built; A[p^1] free (prev done)

        if (ch + 2 < NKC) STAGE_B(ch + 2, (ch + 2) % NSTAGE);
        if (ch + 1 < NKC) {
            BUILD_A(xn, p ^ 1);
            if (ch + 2 < NKC) LDX(ch + 2, xn);
        }

        // compute chunk ch: two k16 steps
#pragma unroll
        for (int ksx = 0; ksx < 2; ksx++) {
            uint32_t af[2][4], bf_[4][4];
#pragma unroll
            for (int mt = 0; mt < 2; mt++)
                ldsm4(af[mt], aLd + p * IMGA + mt * (16 * AROW) + ksx * 32);
#pragma unroll
            for (int q = 0; q < 4; q++)
                ldsm4(bf_[q], bLd + st * IMGB + q * (16 * AROW) + ksx * 32);
#pragma unroll
            for (int mt = 0; mt < 2; mt++)
#pragma unroll
                for (int q = 0; q < 4; q++) {
                    mma16816(acc[mt][q * 2 + 0], af[mt], bf_[q][0], bf_[q][1]);
                    mma16816(acc[mt][q * 2 + 1], af[mt], bf_[q][2], bf_[q][3]);
                }
        }
    }

    // ---- write partial sums ----
    {
        float* part = &g_partial[ks][b0 * Ndim];
        const int rb = wm * 32 + (lane >> 2);
        const int cb = wn * 64 + (lane & 3) * 2;
#pragma unroll
        for (int mt = 0; mt < 2; mt++)
#pragma unroll
            for (int nt = 0; nt < 8; nt++) {
                int rr = rb + mt * 16, cc = cb + nt * 8;
                *(float2*)&part[rr * Ndim + cc] =
                    make_float2(acc[mt][nt][0], acc[mt][nt][1]);
                *(float2*)&part[(rr + 8) * Ndim + cc] =
                    make_float2(acc[mt][nt][2], acc[mt][nt][3]);
            }
    }

    // ---- last CTA of this m-tile finalizes ----
    __threadfence();
    __syncthreads();
    if (tid == 0)
        s_last = (atomicAdd(&g_cnt[mtile], 1) == KSPLIT - 1);
    __syncthreads();

    if (s_last) {
        if (tid == 0) g_cnt[mtile] = 0;     // self-reset for graph replay
#pragma unroll
        for (int h = 0; h < 16; h++) {      // 64 x 128 floats per tile
            int o = b0 * Ndim + h * 512 + tid * 4;
            float4 t0 = *(const float4*)&g_partial[0][o];
            float4 t1 = *(const float4*)&g_partial[1][o];
            float4 t2 = *(const float4*)&g_partial[2][o];
            float4 t3 = *(const float4*)&g_partial[3][o];
            float4 t4 = *(const float4*)&g_partial[4][o];
            float4 t5 = *(const float4*)&g_partial[5][o];
            float4 t6 = *(const float4*)&g_partial[6][o];
            float4 t7 = *(const float4*)&g_partial[7][o];
            float4 v;
            v.x = __fdividef(-1.0f, (((t0.x + t1.x) + (t2.x + t3.x)) +
                                     ((t4.x + t5.x) + (t6.x + t7.x))) - 1.0f);
            v.y = __fdividef(-1.0f, (((t0.y + t1.y) + (t2.y + t3.y)) +
                                     ((t4.y + t5.y) + (t6.y + t7.y))) - 1.0f);
            v.z = __fdividef(-1.0f, (((t0.z + t1.z) + (t2.z + t3.z)) +
                                     ((t4.z + t5.z) + (t6.z + t7.z))) - 1.0f);
            v.w = __fdividef(-1.0f, (((t0.w + t1.w) + (t2.w + t3.w)) +
                                     ((t4.w + t5.w) + (t6.w + t7.w))) - 1.0f);
            *(float4*)&out[o] = v;
        }
    }
}

extern "C" void kernel_launch(void* const* d_in, const int* in_sizes, int n_in,
                              void* d_out, int out_size) {
    const float* x = (const float*)d_in[0];   // (4096, 512)
    const float* W = (const float*)d_in[1];   // (128, 512)
    float* out = (float*)d_out;               // (4096, 128)
    (void)in_sizes; (void)n_in; (void)out_size;

    prep_w<<<8 * NKC, 256>>>(W);                        // 128 CTAs
    conj_mma<<<NMT * KSPLIT, 128>>>(x, out);            // 512 CTAs
}

// round 17
// speedup vs baseline: 1.1624x; 1.1624x over previous
#include <cuda_runtime.h>
#include <cuda_bf16.h>
#include <cstdint>

// Hybrid ConjunctionLayer: out[b,j] = -1/(-1 + sum_k ln(1 - (1-x)W)).
// Two saturated engines run CONCURRENTLY in one heterogeneous kernel:
//  - rows [0, 1856): bf16 mma.sync GEMM over the 8-slot Mercator series
//    (validated R16 path; tensor-pipe wall ~31us solo for all rows)
//  - rows [1856, 4096): packed-f32x2 FMUL product chains + log2 flush
//    (validated R9 path; fp32-datapath wall ~31us solo for all rows)
// Disjoint pipes (tensor vs fma), shared L1 ~= 100%: near-additive throughput.

#define Bdim 4096
#define Ddim 512
#define Ndim 128

// ---- row split ----
#define RG    1856
#define NMTG  (RG / 64)        // 29 GEMM m-tiles
#define NGEMM (NMTG * 8)       // 232 GEMM CTAs (8 series slots each)
#define RF    (Bdim - RG)      // 2240
#define NTF   (RF / 8)         // 280 FFMA tiles
#define NFF   (NTF * 4)        // 1120 FFMA CTAs (4-way K-split)

// ---- GEMM params (R16) ----
#define MT     64
#define NKC    16
#define AROW   80
#define IMGB   (128 * AROW)    // 10240
#define IMGA   (MT * AROW)     // 5120
#define NSTAGE 3

// ---- FFMA params (R9) ----
#define TBF   8
#define KCF   32
#define SROWX 36
#define XWF   (TBF * SROWX)    // 288 words
#define SWROW 32
#define BUFW  (XWF + Ndim * SWROW)  // 4384 words

#define SMEM_BYTES (NSTAGE * IMGB + 2 * IMGA)   // 40960 >= 2*BUFW*4 = 35072

__device__ uint4 g_bmat[128 * IMGB / 16];          // B slot images (1.31MB)
__device__ float g_partial[8][Bdim * Ndim];        // GEMM: ks0-7 rows<RG; FFMA: ks0-3 rows>=RG
__device__ int   g_cntg[NMTG];
__device__ int   g_cntf[NTF];

typedef unsigned long long ull;

__device__ __forceinline__ uint32_t pack_bf16x2(float lo, float hi) {
    uint32_t d;
    asm("cvt.rn.bf16x2.f32 %0, %1, %2;" : "=r"(d) : "f"(hi), "f"(lo));
    return d;
}
__device__ __forceinline__ void cp16(uint32_t dst, const void* src) {
    asm volatile("cp.async.cg.shared.global [%0], [%1], 16;" :: "r"(dst), "l"(src));
}
__device__ __forceinline__ void ldsm4(uint32_t* r, uint32_t addr) {
    asm volatile("ldmatrix.sync.aligned.m8n8.x4.shared.b16 {%0,%1,%2,%3}, [%4];"
                 : "=r"(r[0]), "=r"(r[1]), "=r"(r[2]), "=r"(r[3]) : "r"(addr));
}
__device__ __forceinline__ void mma16816(float* c, const uint32_t* A,
                                         uint32_t b0, uint32_t b1) {
    asm volatile(
        "mma.sync.aligned.m16n8k16.row.col.f32.bf16.bf16.f32 "
        "{%0,%1,%2,%3}, {%4,%5,%6,%7}, {%8,%9}, {%0,%1,%2,%3};"
        : "+f"(c[0]), "+f"(c[1]), "+f"(c[2]), "+f"(c[3])
        : "r"(A[0]), "r"(A[1]), "r"(A[2]), "r"(A[3]), "r"(b0), "r"(b1));
}
__device__ __forceinline__ ull fma2(ull a, ull b, ull c) {
    ull d; asm("fma.rn.f32x2 %0, %1, %2, %3;" : "=l"(d) : "l"(a), "l"(b), "l"(c));
    return d;
}
__device__ __forceinline__ ull mul2(ull a, ull b) {
    ull d; asm("mul.rn.f32x2 %0, %1, %2;" : "=l"(d) : "l"(a), "l"(b));
    return d;
}
__device__ __forceinline__ void unpack2(ull v, float& lo, float& hi) {
    asm("mov.b64 {%0, %1}, %2;" : "=f"(lo), "=f"(hi) : "l"(v));
}

// ---- B slot images (validated): img = t*NKC + kc ----
__global__ void prep_w(const float* __restrict__ W) {
    int img = blockIdx.x;
    int t = img >> 4, kc = img & 15;
    int r = threadIdx.x >> 1, half = threadIdx.x & 1;
    const float* wp = &W[r * Ddim + kc * 32 + half * 16];
    uint32_t pk[8];
#pragma unroll
    for (int i = 0; i < 8; i++) {
        float w0 = wp[2 * i], w1 = wp[2 * i + 1];
        float v0, v1;
        switch (t) {
            case 0: case 2: v0 = w0; v1 = w1; break;
            case 1:
                v0 = w0 - __bfloat162float(__float2bfloat16(w0));
                v1 = w1 - __bfloat162float(__float2bfloat16(w1));
                break;
            case 3: v0 = -0.5f * w0 * w0; v1 = -0.5f * w1 * w1; break;
            case 4: v0 = w0 * w0 * w0 * (1.0f / 3.0f);
                    v1 = w1 * w1 * w1 * (1.0f / 3.0f); break;
            case 5: { float a2 = w0 * w0, b2 = w1 * w1;
                      v0 = -0.25f * a2 * a2; v1 = -0.25f * b2 * b2; } break;
            case 6: { float a2 = w0 * w0, b2 = w1 * w1;
                      v0 = a2 * a2 * w0 * 0.2f; v1 = b2 * b2 * w1 * 0.2f; } break;
            default: { float a2 = w0 * w0, b2 = w1 * w1;
                       v0 = -a2 * a2 * a2 * (1.0f / 6.0f);
                       v1 = -b2 * b2 * b2 * (1.0f / 6.0f); } break;
        }
        pk[i] = pack_bf16x2(v0, v1);
    }
    char* dst = (char*)g_bmat + img * IMGB + r * AROW + half * 32;
    ((uint4*)dst)[0] = make_uint4(pk[0], pk[1], pk[2], pk[3]);
    ((uint4*)(dst + 16))[0] = make_uint4(pk[4], pk[5], pk[6], pk[7]);
}

__global__ __launch_bounds__(128, 4)
void conj_fused(const float* __restrict__ x, const float* __restrict__ W,
                float* __restrict__ out) {
    __shared__ __align__(128) char smem[SMEM_BYTES];
    __shared__ int s_last;
    const int tid = threadIdx.x;
    const int bid = blockIdx.x;

    if (bid < NGEMM) {
        // ================= GEMM path (rows 0..RG-1), validated R16 =========
        const int wid = tid >> 5, lane = tid & 31;
        const int mtile = bid >> 3, ks = bid & 7;
        const int b0 = mtile * MT;
        const int wm = wid >> 1, wn = wid & 1;

        const uint32_t sb = (uint32_t)__cvta_generic_to_shared(smem);
        const uint32_t sA = sb + NSTAGE * IMGB;
        const uint32_t bLd = sb + (wn * 64 + (lane & 7) + ((lane >> 1) & 8)) * AROW
                                + ((lane & 8) << 1);
        const uint32_t aLd = sA + (wm * 32 + (lane & 15)) * AROW + (lane & 16);
        const uint32_t aSts = sA + (tid >> 1) * AROW + (tid & 1) * 32;

        float acc[2][8][4];
#pragma unroll
        for (int mt = 0; mt < 2; mt++)
#pragma unroll
            for (int nt = 0; nt < 8; nt++)
#pragma unroll
                for (int c = 0; c < 4; c++) acc[mt][nt][c] = 0.0f;

        const float* xrow = &x[(b0 + (tid >> 1)) * Ddim + (tid & 1) * 16];
        float4 xc[4], xn[4];

#define LDX(KC, D)                                                            \
    do {                                                                      \
        _Pragma("unroll")                                                     \
        for (int q = 0; q < 4; q++)                                           \
            (D)[q] = *(const float4*)&xrow[(KC) * 32 + q * 4];                \
    } while (0)

#define BUILD_A(SRC, P)                                                       \
    do {                                                                      \
        float a_[16], st[16];                                                 \
        _Pragma("unroll")                                                     \
        for (int q = 0; q < 4; q++) {                                         \
            a_[4*q+0] = (SRC)[q].x - 1.0f; a_[4*q+1] = (SRC)[q].y - 1.0f;     \
            a_[4*q+2] = (SRC)[q].z - 1.0f; a_[4*q+3] = (SRC)[q].w - 1.0f;     \
        }                                                                     \
        if (ks <= 1) {                                                        \
            _Pragma("unroll") for (int i = 0; i < 16; i++) st[i] = a_[i];     \
        } else if (ks == 2) {                                                 \
            _Pragma("unroll") for (int i = 0; i < 16; i++)                    \
                st[i] = a_[i] - __bfloat162float(__float2bfloat16(a_[i]));    \
        } else if (ks == 3) {                                                 \
            _Pragma("unroll") for (int i = 0; i < 16; i++)                    \
                st[i] = a_[i] * a_[i];                                        \
        } else if (ks == 4) {                                                 \
            _Pragma("unroll") for (int i = 0; i < 16; i++)                    \
                st[i] = a_[i] * a_[i] * a_[i];                                \
        } else if (ks == 5) {                                                 \
            _Pragma("unroll") for (int i = 0; i < 16; i++)                    \
                { float t2 = a_[i] * a_[i]; st[i] = t2 * t2; }                \
        } else if (ks == 6) {                                                 \
            _Pragma("unroll") for (int i = 0; i < 16; i++)                    \
                { float t2 = a_[i] * a_[i]; st[i] = t2 * t2 * a_[i]; }        \
        } else {                                                              \
            _Pragma("unroll") for (int i = 0; i < 16; i++)                    \
                { float t3 = a_[i] * a_[i] * a_[i]; st[i] = t3 * t3; }        \
        }                                                                     \
        uint32_t pk[8];                                                       \
        _Pragma("unroll") for (int i = 0; i < 8; i++)                         \
            pk[i] = pack_bf16x2(st[2*i], st[2*i+1]);                          \
        uint32_t ad = aSts + (P) * IMGA;                                      \
        asm volatile("st.shared.v4.b32 [%0], {%1,%2,%3,%4};"                  \
                     :: "r"(ad), "r"(pk[0]), "r"(pk[1]), "r"(pk[2]), "r"(pk[3])); \
        asm volatile("st.shared.v4.b32 [%0], {%1,%2,%3,%4};"                  \
                     :: "r"(ad + 16), "r"(pk[4]), "r"(pk[5]), "r"(pk[6]), "r"(pk[7])); \
    } while (0)

#define STAGE_B(KC, ST)                                                       \
    do {                                                                      \
        const char* src = (const char*)g_bmat + (ks * NKC + (KC)) * IMGB;     \
        _Pragma("unroll")                                                     \
        for (int q = 0; q < 5; q++) {                                         \
            int idx = tid + q * 128;                                          \
            if (idx < IMGB / 16)                                              \
                cp16(sb + (ST) * IMGB + idx * 16, src + idx * 16);            \
        }                                                                     \
        asm volatile("cp.async.commit_group;");                               \
    } while (0)

        LDX(0, xc);
        BUILD_A(xc, 0);
        STAGE_B(0, 0);
        STAGE_B(1, 1);
        LDX(1, xn);

        for (int ch = 0; ch < NKC; ch++) {
            const int st = ch % NSTAGE;
            const int p  = ch & 1;
            asm volatile("cp.async.wait_group 1;");
            __syncthreads();

            if (ch + 2 < NKC) STAGE_B(ch + 2, (ch + 2) % NSTAGE);
            if (ch + 1 < NKC) {
                BUILD_A(xn, p ^ 1);
                if (ch + 2 < NKC) LDX(ch + 2, xn);
            }

#pragma unroll
            for (int ksx = 0; ksx < 2; ksx++) {
                uint32_t af[2][4], bf_[4][4];
#pragma unroll
                for (int mt = 0; mt < 2; mt++)
                    ldsm4(af[mt], aLd + p * IMGA + mt * (16 * AROW) + ksx * 32);
#pragma unroll
                for (int q = 0; q < 4; q++)
                    ldsm4(bf_[q], bLd + st * IMGB + q * (16 * AROW) + ksx * 32);
#pragma unroll
                for (int mt = 0; mt < 2; mt++)
#pragma unroll
                    for (int q = 0; q < 4; q++) {
                        mma16816(acc[mt][q * 2 + 0], af[mt], bf_[q][0], bf_[q][1]);
                        mma16816(acc[mt][q * 2 + 1], af[mt], bf_[q][2], bf_[q][3]);
                    }
            }
        }

        {
            float* part = &g_partial[ks][b0 * Ndim];
            const int rb = wm * 32 + (lane >> 2);
            const int cb = wn * 64 + (lane & 3) * 2;
#pragma unroll
            for (int mt = 0; mt < 2; mt++)
#pragma unroll
                for (int nt = 0; nt < 8; nt++) {
                    int rr = rb + mt * 16, cc = cb + nt * 8;
                    *(float2*)&part[rr * Ndim + cc] =
                        make_float2(acc[mt][nt][0], acc[mt][nt][1]);
                    *(float2*)&part[(rr + 8) * Ndim + cc] =
                        make_float2(acc[mt][nt][2], acc[mt][nt][3]);
                }
        }

        __threadfence();
        __syncthreads();
        if (tid == 0)
            s_last = (atomicAdd(&g_cntg[mtile], 1) == 7);
        __syncthreads();

        if (s_last) {
            if (tid == 0) g_cntg[mtile] = 0;
#pragma unroll
            for (int h = 0; h < 16; h++) {
                int o = b0 * Ndim + h * 512 + tid * 4;
                float4 t0 = *(const float4*)&g_partial[0][o];
                float4 t1 = *(const float4*)&g_partial[1][o];
                float4 t2 = *(const float4*)&g_partial[2][o];
                float4 t3 = *(const float4*)&g_partial[3][o];
                float4 t4 = *(const float4*)&g_partial[4][o];
                float4 t5 = *(const float4*)&g_partial[5][o];
                float4 t6 = *(const float4*)&g_partial[6][o];
                float4 t7 = *(const float4*)&g_partial[7][o];
                float4 v;
                v.x = __fdividef(-1.0f, (((t0.x + t1.x) + (t2.x + t3.x)) +
                                         ((t4.x + t5.x) + (t6.x + t7.x))) - 1.0f);
                v.y = __fdividef(-1.0f, (((t0.y + t1.y) + (t2.y + t3.y)) +
                                         ((t4.y + t5.y) + (t6.y + t7.y))) - 1.0f);
                v.z = __fdividef(-1.0f, (((t0.z + t1.z) + (t2.z + t3.z)) +
                                         ((t4.z + t5.z) + (t6.z + t7.z))) - 1.0f);
                v.w = __fdividef(-1.0f, (((t0.w + t1.w) + (t2.w + t3.w)) +
                                         ((t4.w + t5.w) + (t6.w + t7.w))) - 1.0f);
                *(float4*)&out[o] = v;
            }
        }
    } else {
        // ================= FFMA path (rows RG..4095), validated R9 =========
        float* smf = (float*)smem;
        const int fid   = bid - NGEMM;
        const int tile  = fid >> 2;
        const int ksf   = fid & 3;
        const int b_blk = RG + tile * TBF;
        const int kbase = ksf * 128;          // K-quarter
        const int tj    = tid >> 2;
        const int tb    = tid & 3;
        const int j0    = tj * 4;
        const int tj7   = tj & 7;

        const ull ONE2 = 0x3F8000003F800000ull;

        ull   prod[2][4];
        float lsum[2][4];
#pragma unroll
        for (int r = 0; r < 2; r++)
#pragma unroll
            for (int c = 0; c < 4; c++) { prod[r][c] = ONE2; lsum[r][c] = 0.0f; }

        const uint32_t sbase = (uint32_t)__cvta_generic_to_shared(smem);

        int wrow[8], wc4[8], wc4s[8];
#pragma unroll
        for (int t = 0; t < 8; t++) {
            int idx = tid + t * 128;
            wrow[t] = idx >> 3;
            wc4[t]  = idx & 7;
            wc4s[t] = wc4[t] ^ ((wrow[t] >> 2) & 7);
        }
        const int xrowi = tid >> 3;
        const int xc4i  = tid & 7;
        const bool xth  = (tid < 64);

#define STAGE_WF(CH, P)                                                       \
    do {                                                                      \
        int k0 = kbase + (CH) * KCF;                                          \
        unsigned bofs = sbase + (P) * (BUFW * 4);                             \
        _Pragma("unroll")                                                     \
        for (int t = 0; t < 8; t++)                                           \
            cp16(bofs + (XWF + wrow[t] * SWROW + wc4s[t] * 4) * 4,            \
                 &W[wrow[t] * Ddim + k0 + wc4[t] * 4]);                       \
        asm volatile("cp.async.commit_group;");                               \
    } while (0)

#define LDG_XF(CH, DST)                                                       \
    do {                                                                      \
        if (xth) {                                                            \
            float4 v = *(const float4*)&x[(b_blk + xrowi) * Ddim +            \
                                          kbase + (CH) * KCF + xc4i * 4];     \
            (DST) = make_float4(v.x - 1.0f, v.y - 1.0f, v.z - 1.0f, v.w - 1.0f); \
        }                                                                     \
    } while (0)

#define STS_XF(P, SRC)                                                        \
    do {                                                                      \
        if (xth)                                                              \
            *(float4*)&smf[(P) * BUFW + xrowi * SROWX + xc4i * 4] = (SRC);    \
    } while (0)

        float4 pxa, pxb;
        LDG_XF(0, pxa);
        STS_XF(0, pxa);
        STAGE_WF(0, 0);
        LDG_XF(1, pxa);

        for (int ch = 0; ch < 4; ch++) {
            const int p = ch & 1;
            asm volatile("cp.async.wait_group 0;");
            __syncthreads();

            if (ch + 1 < 4) {
                STS_XF(p ^ 1, pxa);
                STAGE_WF(ch + 1, p ^ 1);
                if (ch + 2 < 4) LDG_XF(ch + 2, pxb);
            }

            const float* bx_s = &smf[p * BUFW];
            const float* bw_s = &smf[p * BUFW + XWF + j0 * SWROW];

#pragma unroll
            for (int kk = 0; kk < KCF; kk += 4) {
                ulonglong2 av0 = *(const ulonglong2*)&bx_s[tb * SROWX + kk];
                ulonglong2 av1 = *(const ulonglong2*)&bx_s[(tb + 4) * SROWX + kk];
                const float* wp = bw_s + ((((kk >> 2) ^ tj7) << 2));
#pragma unroll
                for (int c = 0; c < 4; c++) {
                    ulonglong2 wv = *(const ulonglong2*)&wp[c * SWROW];
                    prod[0][c] = mul2(prod[0][c], fma2((ull)av0.x, wv.x, ONE2));
                    prod[0][c] = mul2(prod[0][c], fma2((ull)av0.y, wv.y, ONE2));
                    prod[1][c] = mul2(prod[1][c], fma2((ull)av1.x, wv.x, ONE2));
                    prod[1][c] = mul2(prod[1][c], fma2((ull)av1.y, wv.y, ONE2));
                }
            }

            if (ch & 1) {
#pragma unroll
                for (int r = 0; r < 2; r++)
#pragma unroll
                    for (int c = 0; c < 4; c++) {
                        float lo, hi;
                        unpack2(prod[r][c], lo, hi);
                        lsum[r][c] += __log2f(lo * hi);
                        prod[r][c] = ONE2;
                    }
            }
            pxa = pxb;
        }

        {
            float* part = &g_partial[ksf][0];
#pragma unroll
            for (int r = 0; r < 2; r++) {
                int b = b_blk + tb + r * 4;
                *(float4*)&part[b * Ndim + j0] =
                    make_float4(lsum[r][0], lsum[r][1], lsum[r][2], lsum[r][3]);
            }
        }

        __threadfence();
        __syncthreads();
        if (tid == 0)
            s_last = (atomicAdd(&g_cntf[tile], 1) == 3);
        __syncthreads();

        if (s_last) {
            if (tid == 0) g_cntf[tile] = 0;
            const float LN2 = 0.6931471805599453f;
            int f   = tid * 8;
            int row = f >> 7;
            int col = f & 127;
            int o   = (b_blk + row) * Ndim + col;
#pragma unroll
            for (int h = 0; h < 2; h++) {
                int oo = o + h * 4;
                float4 s0 = *(const float4*)&g_partial[0][oo];
                float4 s1 = *(const float4*)&g_partial[1][oo];
                float4 s2 = *(const float4*)&g_partial[2][oo];
                float4 s3 = *(const float4*)&g_partial[3][oo];
                float4 v;
                v.x = __fdividef(-1.0f, ((s0.x + s1.x) + (s2.x + s3.x)) * LN2 - 1.0f);
                v.y = __fdividef(-1.0f, ((s0.y + s1.y) + (s2.y + s3.y)) * LN2 - 1.0f);
                v.z = __fdividef(-1.0f, ((s0.z + s1.z) + (s2.z + s3.z)) * LN2 - 1.0f);
                v.w = __fdividef(-1.0f, ((s0.w + s1.w) + (s2.w + s3.w)) * LN2 - 1.0f);
                *(float4*)&out[oo] = v;
            }
        }
    }
}

extern "C" void kernel_launch(void* const* d_in, const int* in_sizes, int n_in,
                              void* d_out, int out_size) {
    const float* x = (const float*)d_in[0];   // (4096, 512)
    const float* W = (const float*)d_in[1];   // (128, 512)
    float* out = (float*)d_out;               // (4096, 128)
    (void)in_sizes; (void)n_in; (void)out_size;

    prep_w<<<128, 256>>>(W);                          // B slot images
    conj_fused<<<NGEMM + NFF, 128>>>(x, W, out);      // 232 GEMM + 1120 FFMA CTAs
}